// round 1
// baseline (speedup 1.0000x reference)
#include <cuda_runtime.h>
#include <cstddef>

#define BB 8
#define SS 512
#define CC 12
#define DD 512
#define HH 8
#define FF 2048
#define LL 4
#define DKH 64
#define NT (BB*SS)   /* 4096 tokens */

// ---------------- scratch (no allocations allowed) ----------------
__device__ float g_x  [NT*DD];
__device__ float g_q  [NT*DD];
__device__ float g_k  [NT*DD];
__device__ float g_v  [NT*DD];
__device__ float g_ctx[NT*DD];
__device__ float g_t  [NT*DD];
__device__ float g_h  [NT*FF];

// ---------------- embed: x = enc @ val_w + val_b + pos ----------------
__global__ void embed_kernel(const float* __restrict__ enc, const float* __restrict__ vw,
                             const float* __restrict__ vb, const float* __restrict__ pos,
                             float* __restrict__ x) {
    int n = blockIdx.y;
    int d = blockIdx.x * 128 + threadIdx.x;
    int s = n & (SS - 1);
    float acc = vb[d] + pos[s * DD + d];
    const float* er = enc + n * CC;
#pragma unroll
    for (int c = 0; c < CC; c++) acc += er[c] * vw[c * DD + d];
    x[n * DD + d] = acc;
}

// ---------------- SGEMM: C = act(A[M,K] @ W[K,N] + bias (+ res)) ----------------
// BM=BN=128, BK=8, 256 threads, 8x8 per thread.
template<int ACT, int HAS_RES>
__global__ __launch_bounds__(256) void sgemm_kernel(
    const float* __restrict__ A, const float* __restrict__ W,
    const float* __restrict__ bias, const float* __restrict__ res,
    float* __restrict__ C, int M, int Ncols, int K) {
    __shared__ float As[8][128];
    __shared__ float Bs[8][128];
    int tid = threadIdx.x;
    int brow = blockIdx.y * 128, bcol = blockIdx.x * 128;
    int ty = tid >> 4, tx = tid & 15;

    float acc[8][8];
#pragma unroll
    for (int i = 0; i < 8; i++)
#pragma unroll
        for (int j = 0; j < 8; j++) acc[i][j] = 0.f;

    int ar = tid >> 1;              // 0..127
    int ak = (tid & 1) << 2;        // 0 or 4
    int bk = tid >> 5;              // 0..7
    int bc = (tid & 31) << 2;       // 0..124
    const float* Aptr = A + (size_t)(brow + ar) * K + ak;
    const float* Bptr = W + (size_t)bk * Ncols + bcol + bc;

    for (int kt = 0; kt < K; kt += 8) {
        float4 a4 = *(const float4*)(Aptr + kt);
        float4 b4 = *(const float4*)(Bptr + (size_t)kt * Ncols);
        As[ak + 0][ar] = a4.x; As[ak + 1][ar] = a4.y;
        As[ak + 2][ar] = a4.z; As[ak + 3][ar] = a4.w;
        *(float4*)&Bs[bk][bc] = b4;
        __syncthreads();
#pragma unroll
        for (int kk = 0; kk < 8; kk++) {
            float ra[8], rb[8];
            *(float4*)(ra)     = *(const float4*)&As[kk][ty * 8];
            *(float4*)(ra + 4) = *(const float4*)&As[kk][ty * 8 + 4];
            *(float4*)(rb)     = *(const float4*)&Bs[kk][tx * 8];
            *(float4*)(rb + 4) = *(const float4*)&Bs[kk][tx * 8 + 4];
#pragma unroll
            for (int i = 0; i < 8; i++)
#pragma unroll
                for (int j = 0; j < 8; j++) acc[i][j] += ra[i] * rb[j];
        }
        __syncthreads();
    }
    // epilogue
#pragma unroll
    for (int i = 0; i < 8; i++) {
        int gm = brow + ty * 8 + i;
#pragma unroll
        for (int j = 0; j < 8; j += 4) {
            int gn = bcol + tx * 8 + j;
            float4 bsv = *(const float4*)&bias[gn];
            float4 o;
            o.x = acc[i][j + 0] + bsv.x;
            o.y = acc[i][j + 1] + bsv.y;
            o.z = acc[i][j + 2] + bsv.z;
            o.w = acc[i][j + 3] + bsv.w;
            if (HAS_RES) {
                float4 r4 = *(const float4*)&res[(size_t)gm * Ncols + gn];
                o.x += r4.x; o.y += r4.y; o.z += r4.z; o.w += r4.w;
            }
            if (ACT) {
                o.x = fmaxf(o.x, 0.f); o.y = fmaxf(o.y, 0.f);
                o.z = fmaxf(o.z, 0.f); o.w = fmaxf(o.w, 0.f);
            }
            *(float4*)&C[(size_t)gm * Ncols + gn] = o;
        }
    }
}

// ---------------- attention scores: out[bh] = q[bh] @ k[bh]^T * scale ----------------
// grid (S/64, S/64, B*H), block 256, 4x4 per thread, K=64 in one shot.
__global__ __launch_bounds__(256) void scores_kernel(
    const float* __restrict__ q, const float* __restrict__ k,
    float* __restrict__ out, float scale) {
    int bh = blockIdx.z; int b = bh >> 3, h = bh & 7;
    int q0 = blockIdx.y * 64, k0 = blockIdx.x * 64;
    __shared__ float sQ[64][65];
    __shared__ float sK[64][65];
    const float* qb = q + (size_t)(b * SS + q0) * DD + h * DKH;
    const float* kb = k + (size_t)(b * SS + k0) * DD + h * DKH;
    int tid = threadIdx.x;
    int lr = tid >> 2;            // 0..63
    int lc = (tid & 3) * 16;      // 0,16,32,48
#pragma unroll
    for (int i = 0; i < 16; i += 4) {
        float4 a = *(const float4*)(qb + (size_t)lr * DD + lc + i);
        sQ[lr][lc + i + 0] = a.x; sQ[lr][lc + i + 1] = a.y;
        sQ[lr][lc + i + 2] = a.z; sQ[lr][lc + i + 3] = a.w;
        float4 c = *(const float4*)(kb + (size_t)lr * DD + lc + i);
        sK[lr][lc + i + 0] = c.x; sK[lr][lc + i + 1] = c.y;
        sK[lr][lc + i + 2] = c.z; sK[lr][lc + i + 3] = c.w;
    }
    __syncthreads();
    int ty = tid >> 4, tx = tid & 15;
    float acc[4][4];
#pragma unroll
    for (int i = 0; i < 4; i++)
#pragma unroll
        for (int j = 0; j < 4; j++) acc[i][j] = 0.f;
#pragma unroll 16
    for (int kk = 0; kk < 64; kk++) {
        float ra[4], rb[4];
#pragma unroll
        for (int i = 0; i < 4; i++) ra[i] = sQ[ty * 4 + i][kk];
#pragma unroll
        for (int j = 0; j < 4; j++) rb[j] = sK[tx * 4 + j][kk];
#pragma unroll
        for (int i = 0; i < 4; i++)
#pragma unroll
            for (int j = 0; j < 4; j++) acc[i][j] += ra[i] * rb[j];
    }
    float* ob = out + (size_t)bh * SS * SS;
#pragma unroll
    for (int i = 0; i < 4; i++)
#pragma unroll
        for (int j = 0; j < 4; j++)
            ob[(size_t)(q0 + ty * 4 + i) * SS + k0 + tx * 4 + j] = acc[i][j] * scale;
}

// ---------------- softmax: in-place over rows of 512 (warp per row) ----------------
__global__ void softmax_kernel(float* __restrict__ attn) {
    int row = blockIdx.x * 8 + (threadIdx.x >> 5);
    int lane = threadIdx.x & 31;
    float4* p = (float4*)(attn + (size_t)row * SS);
    float4 v[4];
#pragma unroll
    for (int c = 0; c < 4; c++) v[c] = p[lane + c * 32];
    float mx = -1e30f;
#pragma unroll
    for (int c = 0; c < 4; c++) {
        mx = fmaxf(mx, fmaxf(fmaxf(v[c].x, v[c].y), fmaxf(v[c].z, v[c].w)));
    }
#pragma unroll
    for (int o = 16; o > 0; o >>= 1) mx = fmaxf(mx, __shfl_xor_sync(0xffffffffu, mx, o));
    float s = 0.f;
#pragma unroll
    for (int c = 0; c < 4; c++) {
        v[c].x = __expf(v[c].x - mx); v[c].y = __expf(v[c].y - mx);
        v[c].z = __expf(v[c].z - mx); v[c].w = __expf(v[c].w - mx);
        s += v[c].x + v[c].y + v[c].z + v[c].w;
    }
#pragma unroll
    for (int o = 16; o > 0; o >>= 1) s += __shfl_xor_sync(0xffffffffu, s, o);
    float inv = 1.0f / s;
#pragma unroll
    for (int c = 0; c < 4; c++) {
        v[c].x *= inv; v[c].y *= inv; v[c].z *= inv; v[c].w *= inv;
        p[lane + c * 32] = v[c];
    }
}

// ---------------- ctx: ctx[bh] = attn[bh][512,512] @ v[bh][512,64] ----------------
// grid (S/64, B*H), block 256, BM=64 BN=64 BK=32, 4x4 per thread.
__global__ __launch_bounds__(256) void ctx_kernel(
    const float* __restrict__ attn, const float* __restrict__ v,
    float* __restrict__ ctx) {
    int bh = blockIdx.y; int b = bh >> 3, h = bh & 7;
    int q0 = blockIdx.x * 64;
    __shared__ float sA[64][33];
    __shared__ float sB[32][65];
    int tid = threadIdx.x;
    int ty = tid >> 4, tx = tid & 15;
    float acc[4][4];
#pragma unroll
    for (int i = 0; i < 4; i++)
#pragma unroll
        for (int j = 0; j < 4; j++) acc[i][j] = 0.f;

    const float* ab = attn + (size_t)bh * SS * SS;
    int arow = tid >> 2;          // 0..63
    int acol = (tid & 3) * 8;     // 0..24
    int brow = tid >> 3;          // 0..31
    int bcol = (tid & 7) * 8;     // 0..56

    for (int kt = 0; kt < SS; kt += 32) {
        float4 a0 = *(const float4*)(ab + (size_t)(q0 + arow) * SS + kt + acol);
        float4 a1 = *(const float4*)(ab + (size_t)(q0 + arow) * SS + kt + acol + 4);
        sA[arow][acol + 0] = a0.x; sA[arow][acol + 1] = a0.y;
        sA[arow][acol + 2] = a0.z; sA[arow][acol + 3] = a0.w;
        sA[arow][acol + 4] = a1.x; sA[arow][acol + 5] = a1.y;
        sA[arow][acol + 6] = a1.z; sA[arow][acol + 7] = a1.w;
        const float* vb = v + (size_t)(b * SS + kt + brow) * DD + h * DKH + bcol;
        float4 b0 = *(const float4*)(vb);
        float4 b1 = *(const float4*)(vb + 4);
        sB[brow][bcol + 0] = b0.x; sB[brow][bcol + 1] = b0.y;
        sB[brow][bcol + 2] = b0.z; sB[brow][bcol + 3] = b0.w;
        sB[brow][bcol + 4] = b1.x; sB[brow][bcol + 5] = b1.y;
        sB[brow][bcol + 6] = b1.z; sB[brow][bcol + 7] = b1.w;
        __syncthreads();
#pragma unroll 8
        for (int kk = 0; kk < 32; kk++) {
            float ra[4], rb[4];
#pragma unroll
            for (int i = 0; i < 4; i++) ra[i] = sA[ty * 4 + i][kk];
#pragma unroll
            for (int j = 0; j < 4; j++) rb[j] = sB[kk][tx * 4 + j];
#pragma unroll
            for (int i = 0; i < 4; i++)
#pragma unroll
                for (int j = 0; j < 4; j++) acc[i][j] += ra[i] * rb[j];
        }
        __syncthreads();
    }
#pragma unroll
    for (int i = 0; i < 4; i++)
#pragma unroll
        for (int j = 0; j < 4; j++)
            ctx[(size_t)(b * SS + q0 + ty * 4 + i) * DD + h * DKH + tx * 4 + j] = acc[i][j];
}

// ---------------- LayerNorm (residual already included in input): warp per row ----------------
__global__ void ln_kernel(const float* __restrict__ in, const float* __restrict__ g,
                          const float* __restrict__ b, float* __restrict__ out) {
    int row = blockIdx.x * 8 + (threadIdx.x >> 5);
    int lane = threadIdx.x & 31;
    const float4* p = (const float4*)(in + (size_t)row * DD);
    float4 v[4];
    float s = 0.f;
#pragma unroll
    for (int c = 0; c < 4; c++) {
        v[c] = p[lane + c * 32];
        s += v[c].x + v[c].y + v[c].z + v[c].w;
    }
#pragma unroll
    for (int o = 16; o > 0; o >>= 1) s += __shfl_xor_sync(0xffffffffu, s, o);
    float mean = s * (1.0f / DD);
    float q = 0.f;
#pragma unroll
    for (int c = 0; c < 4; c++) {
        float dx = v[c].x - mean, dy = v[c].y - mean, dz = v[c].z - mean, dw = v[c].w - mean;
        q += dx * dx + dy * dy + dz * dz + dw * dw;
    }
#pragma unroll
    for (int o = 16; o > 0; o >>= 1) q += __shfl_xor_sync(0xffffffffu, q, o);
    float w = rsqrtf(q * (1.0f / DD) + 1e-5f);
    float4* po = (float4*)(out + (size_t)row * DD);
    const float4* pg = (const float4*)g;
    const float4* pb = (const float4*)b;
#pragma unroll
    for (int c = 0; c < 4; c++) {
        float4 g4 = pg[lane + c * 32];
        float4 b4 = pb[lane + c * 32];
        float4 o4;
        o4.x = (v[c].x - mean) * w * g4.x + b4.x;
        o4.y = (v[c].y - mean) * w * g4.y + b4.y;
        o4.z = (v[c].z - mean) * w * g4.z + b4.z;
        o4.w = (v[c].w - mean) * w * g4.w + b4.w;
        po[lane + c * 32] = o4;
    }
}

// ---------------- host driver ----------------
extern "C" void kernel_launch(void* const* d_in, const int* in_sizes, int n_in,
                              void* d_out, int out_size) {
    const float* enc  = (const float*)d_in[0];
    const float* valw = (const float*)d_in[1];
    const float* valb = (const float*)d_in[2];
    const float* pos  = (const float*)d_in[3];
    const float* Wq   = (const float*)d_in[4];
    const float* bq   = (const float*)d_in[5];
    const float* Wk   = (const float*)d_in[6];
    const float* bk   = (const float*)d_in[7];
    const float* Wv   = (const float*)d_in[8];
    const float* bv   = (const float*)d_in[9];
    const float* Wo   = (const float*)d_in[10];
    const float* bo   = (const float*)d_in[11];
    const float* ln1g = (const float*)d_in[12];
    const float* ln1b = (const float*)d_in[13];
    const float* c1w  = (const float*)d_in[14];
    const float* c1b  = (const float*)d_in[15];
    const float* c2w  = (const float*)d_in[16];
    const float* c2b  = (const float*)d_in[17];
    const float* ln2g = (const float*)d_in[18];
    const float* ln2b = (const float*)d_in[19];

    float* out_x = (float*)d_out;
    float* out_attn = out_x + (size_t)NT * DD;

    float *x, *q, *k, *v, *ctx, *t, *h;
    cudaGetSymbolAddress((void**)&x,   g_x);
    cudaGetSymbolAddress((void**)&q,   g_q);
    cudaGetSymbolAddress((void**)&k,   g_k);
    cudaGetSymbolAddress((void**)&v,   g_v);
    cudaGetSymbolAddress((void**)&ctx, g_ctx);
    cudaGetSymbolAddress((void**)&t,   g_t);
    cudaGetSymbolAddress((void**)&h,   g_h);

    embed_kernel<<<dim3(DD / 128, NT), 128>>>(enc, valw, valb, pos, x);

    const float scale = 0.125f;  // 1/sqrt(64)
    dim3 g512(DD / 128, NT / 128);     // N=512 gemms
    dim3 gF(FF / 128, NT / 128);       // N=2048 gemm

    for (int l = 0; l < LL; l++) {
        const float* wq = Wq + (size_t)l * DD * DD;
        const float* wk = Wk + (size_t)l * DD * DD;
        const float* wv = Wv + (size_t)l * DD * DD;
        const float* wo = Wo + (size_t)l * DD * DD;
        float* attn_l = out_attn + (size_t)l * BB * HH * SS * SS;

        sgemm_kernel<0, 0><<<g512, 256>>>(x, wq, bq + l * DD, nullptr, q, NT, DD, DD);
        sgemm_kernel<0, 0><<<g512, 256>>>(x, wk, bk + l * DD, nullptr, k, NT, DD, DD);
        sgemm_kernel<0, 0><<<g512, 256>>>(x, wv, bv + l * DD, nullptr, v, NT, DD, DD);

        scores_kernel<<<dim3(SS / 64, SS / 64, BB * HH), 256>>>(q, k, attn_l, scale);
        softmax_kernel<<<(BB * HH * SS) / 8, 256>>>(attn_l);
        ctx_kernel<<<dim3(SS / 64, BB * HH), 256>>>(attn_l, v, ctx);

        sgemm_kernel<0, 1><<<g512, 256>>>(ctx, wo, bo + l * DD, x, t, NT, DD, DD);
        ln_kernel<<<NT / 8, 256>>>(t, ln1g + l * DD, ln1b + l * DD, x);

        sgemm_kernel<1, 0><<<gF, 256>>>(x, c1w + (size_t)l * DD * FF, c1b + l * FF, nullptr, h, NT, FF, DD);
        sgemm_kernel<0, 1><<<g512, 256>>>(h, c2w + (size_t)l * FF * DD, c2b + l * DD, x, t, NT, DD, FF);

        float* lnout = (l == LL - 1) ? out_x : x;
        ln_kernel<<<NT / 8, 256>>>(t, ln2g + l * DD, ln2b + l * DD, lnout);
    }
}

// round 2
// speedup vs baseline: 1.5198x; 1.5198x over previous
#include <cuda_runtime.h>
#include <cstdint>
#include <cstddef>

#define BB 8
#define SS 512
#define CC 12
#define DD 512
#define HH 8
#define FF 2048
#define LL 4
#define DKH 64
#define NT (BB*SS)   /* 4096 tokens */

// ---------------- scratch (no allocations allowed) ----------------
__device__ float g_x  [NT*DD];
__device__ float g_q  [NT*DD];
__device__ float g_k  [NT*DD];
__device__ float g_v  [NT*DD];
__device__ float g_ctx[NT*DD];
__device__ float g_t  [NT*DD];
__device__ float g_h  [NT*FF];

// ---------------- helpers ----------------
__device__ __forceinline__ uint32_t f2tf(float f) {
    uint32_t u;
    asm("cvt.rna.tf32.f32 %0, %1;" : "=r"(u) : "f"(f));
    return u;
}

__device__ __forceinline__ void mma_tf32(float& c0, float& c1, float& c2, float& c3,
                                         uint32_t a0, uint32_t a1, uint32_t a2, uint32_t a3,
                                         uint32_t b0, uint32_t b1) {
    asm("mma.sync.aligned.m16n8k8.row.col.f32.tf32.tf32.f32 "
        "{%0,%1,%2,%3}, {%4,%5,%6,%7}, {%8,%9}, {%0,%1,%2,%3};"
        : "+f"(c0), "+f"(c1), "+f"(c2), "+f"(c3)
        : "r"(a0), "r"(a1), "r"(a2), "r"(a3), "r"(b0), "r"(b1));
}

// ---------------- embed: x = enc @ val_w + val_b + pos ----------------
__global__ void embed_kernel(const float* __restrict__ enc, const float* __restrict__ vw,
                             const float* __restrict__ vb, const float* __restrict__ pos,
                             float* __restrict__ x) {
    int n = blockIdx.y;
    int d = blockIdx.x * 128 + threadIdx.x;
    int s = n & (SS - 1);
    float acc = vb[d] + pos[s * DD + d];
    const float* er = enc + n * CC;
#pragma unroll
    for (int c = 0; c < CC; c++) acc += er[c] * vw[c * DD + d];
    x[n * DD + d] = acc;
}

// ---------------- tf32 tensor-core GEMM: C = act(A[M,K] @ W[K,N] + bias (+ res)) -----
// BM=128, BN=128, BK=16; 256 threads = 8 warps (4 x 2); warp tile 32x64.
template<int ACT, int HAS_RES>
__global__ __launch_bounds__(256) void mma_gemm(
    const float* __restrict__ A, const float* __restrict__ W,
    const float* __restrict__ bias, const float* __restrict__ res,
    float* __restrict__ C, int M, int N, int K) {
    __shared__ uint32_t As[16][129];   // [k][m], transposed
    __shared__ uint32_t Bs[16][132];   // [k][n]

    int tid = threadIdx.x;
    int lane = tid & 31, warp = tid >> 5;
    int gid = lane >> 2, tig = lane & 3;
    int brow = blockIdx.y * 128, bcol = blockIdx.x * 128;
    int wm = (warp >> 1) * 32, wn = (warp & 1) * 64;

    float c[2][8][4];
#pragma unroll
    for (int mt = 0; mt < 2; mt++)
#pragma unroll
        for (int nt = 0; nt < 8; nt++)
#pragma unroll
            for (int i = 0; i < 4; i++) c[mt][nt][i] = 0.f;

    int am = tid >> 1, akb = (tid & 1) * 8;
    const float* Ap = A + (size_t)(brow + am) * K + akb;
    int bkr = tid >> 5, bn = (tid & 31) * 4;
    const float* Bp = W + (size_t)bkr * N + bcol + bn;

    for (int kt = 0; kt < K; kt += 16) {
        float4 la0 = *(const float4*)(Ap + kt);
        float4 la1 = *(const float4*)(Ap + kt + 4);
        float4 lb0 = *(const float4*)(Bp + (size_t)kt * N);
        float4 lb1 = *(const float4*)(Bp + (size_t)(kt + 8) * N);
        As[akb + 0][am] = f2tf(la0.x); As[akb + 1][am] = f2tf(la0.y);
        As[akb + 2][am] = f2tf(la0.z); As[akb + 3][am] = f2tf(la0.w);
        As[akb + 4][am] = f2tf(la1.x); As[akb + 5][am] = f2tf(la1.y);
        As[akb + 6][am] = f2tf(la1.z); As[akb + 7][am] = f2tf(la1.w);
        Bs[bkr][bn + 0] = f2tf(lb0.x); Bs[bkr][bn + 1] = f2tf(lb0.y);
        Bs[bkr][bn + 2] = f2tf(lb0.z); Bs[bkr][bn + 3] = f2tf(lb0.w);
        Bs[bkr + 8][bn + 0] = f2tf(lb1.x); Bs[bkr + 8][bn + 1] = f2tf(lb1.y);
        Bs[bkr + 8][bn + 2] = f2tf(lb1.z); Bs[bkr + 8][bn + 3] = f2tf(lb1.w);
        __syncthreads();
#pragma unroll
        for (int kk = 0; kk < 16; kk += 8) {
            uint32_t af[2][4], bf[8][2];
#pragma unroll
            for (int mt = 0; mt < 2; mt++) {
                int rb = wm + mt * 16 + gid;
                af[mt][0] = As[kk + tig][rb];
                af[mt][1] = As[kk + tig][rb + 8];
                af[mt][2] = As[kk + 4 + tig][rb];
                af[mt][3] = As[kk + 4 + tig][rb + 8];
            }
#pragma unroll
            for (int nt = 0; nt < 8; nt++) {
                int cb = wn + nt * 8 + gid;
                bf[nt][0] = Bs[kk + tig][cb];
                bf[nt][1] = Bs[kk + 4 + tig][cb];
            }
#pragma unroll
            for (int mt = 0; mt < 2; mt++)
#pragma unroll
                for (int nt = 0; nt < 8; nt++)
                    mma_tf32(c[mt][nt][0], c[mt][nt][1], c[mt][nt][2], c[mt][nt][3],
                             af[mt][0], af[mt][1], af[mt][2], af[mt][3],
                             bf[nt][0], bf[nt][1]);
        }
        __syncthreads();
    }
    // epilogue
#pragma unroll
    for (int mt = 0; mt < 2; mt++) {
        int gr0 = brow + wm + mt * 16 + gid;
        int gr1 = gr0 + 8;
#pragma unroll
        for (int nt = 0; nt < 8; nt++) {
            int gc = bcol + wn + nt * 8 + tig * 2;
            float2 bsv = *(const float2*)&bias[gc];
            float2 o0, o1;
            o0.x = c[mt][nt][0] + bsv.x; o0.y = c[mt][nt][1] + bsv.y;
            o1.x = c[mt][nt][2] + bsv.x; o1.y = c[mt][nt][3] + bsv.y;
            if (HAS_RES) {
                float2 r0 = *(const float2*)&res[(size_t)gr0 * N + gc];
                float2 r1 = *(const float2*)&res[(size_t)gr1 * N + gc];
                o0.x += r0.x; o0.y += r0.y;
                o1.x += r1.x; o1.y += r1.y;
            }
            if (ACT) {
                o0.x = fmaxf(o0.x, 0.f); o0.y = fmaxf(o0.y, 0.f);
                o1.x = fmaxf(o1.x, 0.f); o1.y = fmaxf(o1.y, 0.f);
            }
            *(float2*)&C[(size_t)gr0 * N + gc] = o0;
            *(float2*)&C[(size_t)gr1 * N + gc] = o1;
        }
    }
}

// ---------------- fused scores + softmax ----------------
// Block: 512 threads (16 warps: 4 m x 4 n). Computes attn[bh][q0:q0+64][0:512]
// = softmax(Q @ K^T * scale) and writes probs to the output buffer.
__global__ __launch_bounds__(512) void scores_softmax_kernel(
    const float* __restrict__ q, const float* __restrict__ k,
    float* __restrict__ attn) {
    __shared__ uint32_t Qs[64][65];   // [dk][qrow]
    __shared__ uint32_t Ks[64][65];   // [dk][key]
    __shared__ float redm[64][4];
    __shared__ float reds[64][4];

    int bh = blockIdx.y, b = bh >> 3, h = bh & 7;
    int q0 = blockIdx.x * 64;
    int tid = threadIdx.x;
    int lane = tid & 31, warp = tid >> 5;
    int gid = lane >> 2, tig = lane & 3;
    int wm = warp >> 2, wn = warp & 3;

    // load Q tile (64 rows x 64 dk), transposed into Qs[dk][row]
    int qr = tid >> 3, dkb = (tid & 7) * 8;
    {
        const float* qp = q + (size_t)(b * SS + q0 + qr) * DD + h * DKH + dkb;
        float4 t0 = *(const float4*)qp;
        float4 t1 = *(const float4*)(qp + 4);
        Qs[dkb + 0][qr] = f2tf(t0.x); Qs[dkb + 1][qr] = f2tf(t0.y);
        Qs[dkb + 2][qr] = f2tf(t0.z); Qs[dkb + 3][qr] = f2tf(t0.w);
        Qs[dkb + 4][qr] = f2tf(t1.x); Qs[dkb + 5][qr] = f2tf(t1.y);
        Qs[dkb + 6][qr] = f2tf(t1.z); Qs[dkb + 7][qr] = f2tf(t1.w);
    }

    float s[8][2][4];
#pragma unroll
    for (int nc = 0; nc < 8; nc++)
#pragma unroll
        for (int nt = 0; nt < 2; nt++)
#pragma unroll
            for (int i = 0; i < 4; i++) s[nc][nt][i] = 0.f;

    for (int nc = 0; nc < 8; nc++) {
        __syncthreads();
        {
            const float* kp = k + (size_t)(b * SS + nc * 64 + qr) * DD + h * DKH + dkb;
            float4 t0 = *(const float4*)kp;
            float4 t1 = *(const float4*)(kp + 4);
            Ks[dkb + 0][qr] = f2tf(t0.x); Ks[dkb + 1][qr] = f2tf(t0.y);
            Ks[dkb + 2][qr] = f2tf(t0.z); Ks[dkb + 3][qr] = f2tf(t0.w);
            Ks[dkb + 4][qr] = f2tf(t1.x); Ks[dkb + 5][qr] = f2tf(t1.y);
            Ks[dkb + 6][qr] = f2tf(t1.z); Ks[dkb + 7][qr] = f2tf(t1.w);
        }
        __syncthreads();
#pragma unroll
        for (int kk = 0; kk < 64; kk += 8) {
            uint32_t af[4], bf[2][2];
            int rb = wm * 16 + gid;
            af[0] = Qs[kk + tig][rb];
            af[1] = Qs[kk + tig][rb + 8];
            af[2] = Qs[kk + 4 + tig][rb];
            af[3] = Qs[kk + 4 + tig][rb + 8];
#pragma unroll
            for (int nt = 0; nt < 2; nt++) {
                int cb = wn * 16 + nt * 8 + gid;
                bf[nt][0] = Ks[kk + tig][cb];
                bf[nt][1] = Ks[kk + 4 + tig][cb];
            }
#pragma unroll
            for (int nt = 0; nt < 2; nt++)
                mma_tf32(s[nc][nt][0], s[nc][nt][1], s[nc][nt][2], s[nc][nt][3],
                         af[0], af[1], af[2], af[3], bf[nt][0], bf[nt][1]);
        }
    }

    // softmax over the 512 columns of each of the 64 rows
    const float scale = 0.125f;
    int r0 = wm * 16 + gid, r1 = r0 + 8;
    float m0 = -1e30f, m1 = -1e30f;
#pragma unroll
    for (int nc = 0; nc < 8; nc++)
#pragma unroll
        for (int nt = 0; nt < 2; nt++) {
            s[nc][nt][0] *= scale; s[nc][nt][1] *= scale;
            s[nc][nt][2] *= scale; s[nc][nt][3] *= scale;
            m0 = fmaxf(m0, fmaxf(s[nc][nt][0], s[nc][nt][1]));
            m1 = fmaxf(m1, fmaxf(s[nc][nt][2], s[nc][nt][3]));
        }
#pragma unroll
    for (int o = 1; o <= 2; o <<= 1) {
        m0 = fmaxf(m0, __shfl_xor_sync(0xffffffffu, m0, o));
        m1 = fmaxf(m1, __shfl_xor_sync(0xffffffffu, m1, o));
    }
    if (tig == 0) { redm[r0][wn] = m0; redm[r1][wn] = m1; }
    __syncthreads();
    m0 = fmaxf(fmaxf(redm[r0][0], redm[r0][1]), fmaxf(redm[r0][2], redm[r0][3]));
    m1 = fmaxf(fmaxf(redm[r1][0], redm[r1][1]), fmaxf(redm[r1][2], redm[r1][3]));

    float sum0 = 0.f, sum1 = 0.f;
#pragma unroll
    for (int nc = 0; nc < 8; nc++)
#pragma unroll
        for (int nt = 0; nt < 2; nt++) {
            s[nc][nt][0] = __expf(s[nc][nt][0] - m0);
            s[nc][nt][1] = __expf(s[nc][nt][1] - m0);
            s[nc][nt][2] = __expf(s[nc][nt][2] - m1);
            s[nc][nt][3] = __expf(s[nc][nt][3] - m1);
            sum0 += s[nc][nt][0] + s[nc][nt][1];
            sum1 += s[nc][nt][2] + s[nc][nt][3];
        }
#pragma unroll
    for (int o = 1; o <= 2; o <<= 1) {
        sum0 += __shfl_xor_sync(0xffffffffu, sum0, o);
        sum1 += __shfl_xor_sync(0xffffffffu, sum1, o);
    }
    if (tig == 0) { reds[r0][wn] = sum0; reds[r1][wn] = sum1; }
    __syncthreads();
    float inv0 = 1.0f / (reds[r0][0] + reds[r0][1] + reds[r0][2] + reds[r0][3]);
    float inv1 = 1.0f / (reds[r1][0] + reds[r1][1] + reds[r1][2] + reds[r1][3]);

    float* ob = attn + (size_t)bh * SS * SS;
#pragma unroll
    for (int nc = 0; nc < 8; nc++)
#pragma unroll
        for (int nt = 0; nt < 2; nt++) {
            int col = nc * 64 + wn * 16 + nt * 8 + tig * 2;
            float2 o0, o1;
            o0.x = s[nc][nt][0] * inv0; o0.y = s[nc][nt][1] * inv0;
            o1.x = s[nc][nt][2] * inv1; o1.y = s[nc][nt][3] * inv1;
            *(float2*)&ob[(size_t)(q0 + r0) * SS + col] = o0;
            *(float2*)&ob[(size_t)(q0 + r1) * SS + col] = o1;
        }
}

// ---------------- ctx = attn @ V (tf32 mma) ----------------
// Block: 256 threads (8 warps: 4 m x 2 n). BM=64 (q rows), BN=64 (dk), BK=32.
__global__ __launch_bounds__(256) void ctx_mma_kernel(
    const float* __restrict__ attn, const float* __restrict__ v,
    float* __restrict__ ctx) {
    __shared__ uint32_t As[32][65];   // [key][qrow], transposed probs
    __shared__ uint32_t Bs[32][68];   // [key][dk]

    int bh = blockIdx.y, b = bh >> 3, h = bh & 7;
    int q0 = blockIdx.x * 64;
    int tid = threadIdx.x;
    int lane = tid & 31, warp = tid >> 5;
    int gid = lane >> 2, tig = lane & 3;
    int wm = warp >> 1, wn = warp & 1;

    float c[4][4];
#pragma unroll
    for (int nt = 0; nt < 4; nt++)
#pragma unroll
        for (int i = 0; i < 4; i++) c[nt][i] = 0.f;

    const float* ab = attn + (size_t)bh * SS * SS;
    int am = tid >> 2, akb = (tid & 3) * 8;
    int bk = tid >> 3, bnb = (tid & 7) * 8;

    for (int kt = 0; kt < SS; kt += 32) {
        float4 la0 = *(const float4*)(ab + (size_t)(q0 + am) * SS + kt + akb);
        float4 la1 = *(const float4*)(ab + (size_t)(q0 + am) * SS + kt + akb + 4);
        As[akb + 0][am] = f2tf(la0.x); As[akb + 1][am] = f2tf(la0.y);
        As[akb + 2][am] = f2tf(la0.z); As[akb + 3][am] = f2tf(la0.w);
        As[akb + 4][am] = f2tf(la1.x); As[akb + 5][am] = f2tf(la1.y);
        As[akb + 6][am] = f2tf(la1.z); As[akb + 7][am] = f2tf(la1.w);
        const float* vp = v + (size_t)(b * SS + kt + bk) * DD + h * DKH + bnb;
        float4 lb0 = *(const float4*)vp;
        float4 lb1 = *(const float4*)(vp + 4);
        Bs[bk][bnb + 0] = f2tf(lb0.x); Bs[bk][bnb + 1] = f2tf(lb0.y);
        Bs[bk][bnb + 2] = f2tf(lb0.z); Bs[bk][bnb + 3] = f2tf(lb0.w);
        Bs[bk][bnb + 4] = f2tf(lb1.x); Bs[bk][bnb + 5] = f2tf(lb1.y);
        Bs[bk][bnb + 6] = f2tf(lb1.z); Bs[bk][bnb + 7] = f2tf(lb1.w);
        __syncthreads();
#pragma unroll
        for (int kk = 0; kk < 32; kk += 8) {
            uint32_t af[4], bf[4][2];
            int rb = wm * 16 + gid;
            af[0] = As[kk + tig][rb];
            af[1] = As[kk + tig][rb + 8];
            af[2] = As[kk + 4 + tig][rb];
            af[3] = As[kk + 4 + tig][rb + 8];
#pragma unroll
            for (int nt = 0; nt < 4; nt++) {
                int cb = wn * 32 + nt * 8 + gid;
                bf[nt][0] = Bs[kk + tig][cb];
                bf[nt][1] = Bs[kk + 4 + tig][cb];
            }
#pragma unroll
            for (int nt = 0; nt < 4; nt++)
                mma_tf32(c[nt][0], c[nt][1], c[nt][2], c[nt][3],
                         af[0], af[1], af[2], af[3], bf[nt][0], bf[nt][1]);
        }
        __syncthreads();
    }
#pragma unroll
    for (int nt = 0; nt < 4; nt++) {
        int gr0 = b * SS + q0 + wm * 16 + gid;
        int gc = h * DKH + wn * 32 + nt * 8 + tig * 2;
        *(float2*)&ctx[(size_t)gr0 * DD + gc] = make_float2(c[nt][0], c[nt][1]);
        *(float2*)&ctx[(size_t)(gr0 + 8) * DD + gc] = make_float2(c[nt][2], c[nt][3]);
    }
}

// ---------------- LayerNorm (residual already included in input): warp per row ------
__global__ void ln_kernel(const float* __restrict__ in, const float* __restrict__ g,
                          const float* __restrict__ b, float* __restrict__ out) {
    int row = blockIdx.x * 8 + (threadIdx.x >> 5);
    int lane = threadIdx.x & 31;
    const float4* p = (const float4*)(in + (size_t)row * DD);
    float4 v[4];
    float s = 0.f;
#pragma unroll
    for (int c = 0; c < 4; c++) {
        v[c] = p[lane + c * 32];
        s += v[c].x + v[c].y + v[c].z + v[c].w;
    }
#pragma unroll
    for (int o = 16; o > 0; o >>= 1) s += __shfl_xor_sync(0xffffffffu, s, o);
    float mean = s * (1.0f / DD);
    float q = 0.f;
#pragma unroll
    for (int c = 0; c < 4; c++) {
        float dx = v[c].x - mean, dy = v[c].y - mean, dz = v[c].z - mean, dw = v[c].w - mean;
        q += dx * dx + dy * dy + dz * dz + dw * dw;
    }
#pragma unroll
    for (int o = 16; o > 0; o >>= 1) q += __shfl_xor_sync(0xffffffffu, q, o);
    float w = rsqrtf(q * (1.0f / DD) + 1e-5f);
    float4* po = (float4*)(out + (size_t)row * DD);
    const float4* pg = (const float4*)g;
    const float4* pb = (const float4*)b;
#pragma unroll
    for (int c = 0; c < 4; c++) {
        float4 g4 = pg[lane + c * 32];
        float4 b4 = pb[lane + c * 32];
        float4 o4;
        o4.x = (v[c].x - mean) * w * g4.x + b4.x;
        o4.y = (v[c].y - mean) * w * g4.y + b4.y;
        o4.z = (v[c].z - mean) * w * g4.z + b4.z;
        o4.w = (v[c].w - mean) * w * g4.w + b4.w;
        po[lane + c * 32] = o4;
    }
}

// ---------------- host driver ----------------
extern "C" void kernel_launch(void* const* d_in, const int* in_sizes, int n_in,
                              void* d_out, int out_size) {
    const float* enc  = (const float*)d_in[0];
    const float* valw = (const float*)d_in[1];
    const float* valb = (const float*)d_in[2];
    const float* pos  = (const float*)d_in[3];
    const float* Wq   = (const float*)d_in[4];
    const float* bq   = (const float*)d_in[5];
    const float* Wk   = (const float*)d_in[6];
    const float* bk   = (const float*)d_in[7];
    const float* Wv   = (const float*)d_in[8];
    const float* bv   = (const float*)d_in[9];
    const float* Wo   = (const float*)d_in[10];
    const float* bo   = (const float*)d_in[11];
    const float* ln1g = (const float*)d_in[12];
    const float* ln1b = (const float*)d_in[13];
    const float* c1w  = (const float*)d_in[14];
    const float* c1b  = (const float*)d_in[15];
    const float* c2w  = (const float*)d_in[16];
    const float* c2b  = (const float*)d_in[17];
    const float* ln2g = (const float*)d_in[18];
    const float* ln2b = (const float*)d_in[19];

    float* out_x = (float*)d_out;
    float* out_attn = out_x + (size_t)NT * DD;

    float *x, *q, *k, *v, *ctx, *t, *h;
    cudaGetSymbolAddress((void**)&x,   g_x);
    cudaGetSymbolAddress((void**)&q,   g_q);
    cudaGetSymbolAddress((void**)&k,   g_k);
    cudaGetSymbolAddress((void**)&v,   g_v);
    cudaGetSymbolAddress((void**)&ctx, g_ctx);
    cudaGetSymbolAddress((void**)&t,   g_t);
    cudaGetSymbolAddress((void**)&h,   g_h);

    embed_kernel<<<dim3(DD / 128, NT), 128>>>(enc, valw, valb, pos, x);

    dim3 g512(DD / 128, NT / 128);     // N=512 gemms: (4, 32)
    dim3 gF(FF / 128, NT / 128);       // N=2048 gemm: (16, 32)

    for (int l = 0; l < LL; l++) {
        const float* wq = Wq + (size_t)l * DD * DD;
        const float* wk = Wk + (size_t)l * DD * DD;
        const float* wv = Wv + (size_t)l * DD * DD;
        const float* wo = Wo + (size_t)l * DD * DD;
        float* attn_l = out_attn + (size_t)l * BB * HH * SS * SS;

        mma_gemm<0, 0><<<g512, 256>>>(x, wq, bq + l * DD, nullptr, q, NT, DD, DD);
        mma_gemm<0, 0><<<g512, 256>>>(x, wk, bk + l * DD, nullptr, k, NT, DD, DD);
        mma_gemm<0, 0><<<g512, 256>>>(x, wv, bv + l * DD, nullptr, v, NT, DD, DD);

        scores_softmax_kernel<<<dim3(SS / 64, BB * HH), 512>>>(q, k, attn_l);
        ctx_mma_kernel<<<dim3(SS / 64, BB * HH), 256>>>(attn_l, v, ctx);

        mma_gemm<0, 1><<<g512, 256>>>(ctx, wo, bo + l * DD, x, t, NT, DD, DD);
        ln_kernel<<<NT / 8, 256>>>(t, ln1g + l * DD, ln1b + l * DD, x);

        mma_gemm<1, 0><<<gF, 256>>>(x, c1w + (size_t)l * DD * FF, c1b + l * FF, nullptr, h, NT, FF, DD);
        mma_gemm<0, 1><<<g512, 256>>>(h, c2w + (size_t)l * FF * DD, c2b + l * DD, x, t, NT, DD, FF);

        float* lnout = (l == LL - 1) ? out_x : x;
        ln_kernel<<<NT / 8, 256>>>(t, ln2g + l * DD, ln2b + l * DD, lnout);
    }
}

// round 5
// speedup vs baseline: 2.0892x; 1.3746x over previous
#include <cuda_runtime.h>
#include <cstdint>
#include <cstddef>

#define BB 8
#define SS 512
#define CC 12
#define DD 512
#define HH 8
#define FF 2048
#define LL 4
#define DKH 64
#define NT (BB*SS)   /* 4096 tokens */

// ---------------- scratch (no allocations allowed) ----------------
__device__ float g_x  [NT*DD];
__device__ float g_q  [NT*DD];
__device__ float g_k  [NT*DD];
__device__ float g_v  [NT*DD];
__device__ float g_ctx[NT*DD];
__device__ float g_t  [NT*DD];
__device__ float g_h  [NT*FF];

// ---------------- helpers ----------------
__device__ __forceinline__ uint32_t f2tf(float f) {
    uint32_t u;
    asm("cvt.rna.tf32.f32 %0, %1;" : "=r"(u) : "f"(f));
    return u;
}

__device__ __forceinline__ void mma_tf32(float& c0, float& c1, float& c2, float& c3,
                                         uint32_t a0, uint32_t a1, uint32_t a2, uint32_t a3,
                                         uint32_t b0, uint32_t b1) {
    asm("mma.sync.aligned.m16n8k8.row.col.f32.tf32.tf32.f32 "
        "{%0,%1,%2,%3}, {%4,%5,%6,%7}, {%8,%9}, {%0,%1,%2,%3};"
        : "+f"(c0), "+f"(c1), "+f"(c2), "+f"(c3)
        : "r"(a0), "r"(a1), "r"(a2), "r"(a3), "r"(b0), "r"(b1));
}

__device__ __forceinline__ void cp_async16(void* smem_dst, const void* gsrc) {
    uint32_t s = (uint32_t)__cvta_generic_to_shared(smem_dst);
    asm volatile("cp.async.cg.shared.global [%0], [%1], 16;" :: "r"(s), "l"(gsrc));
}
__device__ __forceinline__ void cp_commit() {
    asm volatile("cp.async.commit_group;");
}
template<int N> __device__ __forceinline__ void cp_wait() {
    asm volatile("cp.async.wait_group %0;" :: "n"(N));
}

// ---------------- embed: x = enc @ val_w + val_b + pos ----------------
__global__ void embed_kernel(const float* __restrict__ enc, const float* __restrict__ vw,
                             const float* __restrict__ vb, const float* __restrict__ pos,
                             float* __restrict__ x) {
    int n = blockIdx.y;
    int d = blockIdx.x * 128 + threadIdx.x;
    int s = n & (SS - 1);
    float acc = vb[d] + pos[s * DD + d];
    const float* er = enc + n * CC;
#pragma unroll
    for (int c = 0; c < CC; c++) acc += er[c] * vw[c * DD + d];
    x[n * DD + d] = acc;
}

// ---------------- tf32 tensor-core GEMM, cp.async double-buffered ----------------
// C = act(A[M,K] @ W[K,N] + bias (+ res)). BM=128, BN=128, BK=16, STAGES=2.
// 256 threads = 8 warps (4 m x 2 n); warp tile 32x64.
template<int ACT, int HAS_RES>
__global__ __launch_bounds__(256) void mma_gemm(
    const float* __restrict__ A, const float* __restrict__ W,
    const float* __restrict__ bias, const float* __restrict__ res,
    float* __restrict__ C, int M, int N, int K) {
    __shared__ float As[2][128][20];   // [m][k], pad 16->20 (conflict-free frag loads)
    __shared__ float Bs[2][16][136];   // [k][n], pad 128->136

    int tid = threadIdx.x;
    int lane = tid & 31, warp = tid >> 5;
    int gid = lane >> 2, tig = lane & 3;
    int brow = blockIdx.y * 128, bcol = blockIdx.x * 128;
    int wm = (warp >> 1) * 32, wn = (warp & 1) * 64;

    float c[2][8][4];
#pragma unroll
    for (int mt = 0; mt < 2; mt++)
#pragma unroll
        for (int nt = 0; nt < 8; nt++)
#pragma unroll
            for (int i = 0; i < 4; i++) c[mt][nt][i] = 0.f;

    // cp.async assignments
    int am = tid >> 1, akb = (tid & 1) * 8;            // A: row am, cols akb..akb+7
    int bkr = tid >> 4, bn = (tid & 15) * 8;           // B: k-row bkr, cols bn..bn+7
    const float* Ap = A + (size_t)(brow + am) * K + akb;
    const float* Bp = W + (size_t)bkr * N + bcol + bn;

    const int ktiles = K >> 4;

#define LOAD_TILE(KT, S)                                              \
    do {                                                              \
        const float* _a = Ap + ((KT) << 4);                           \
        cp_async16(&As[S][am][akb],     _a);                          \
        cp_async16(&As[S][am][akb + 4], _a + 4);                      \
        const float* _b = Bp + ((size_t)(KT) << 4) * N;               \
        cp_async16(&Bs[S][bkr][bn],     _b);                          \
        cp_async16(&Bs[S][bkr][bn + 4], _b + 4);                      \
    } while (0)

    LOAD_TILE(0, 0); cp_commit();
    LOAD_TILE(1, 1); cp_commit();

    for (int kt = 0; kt < ktiles; kt++) {
        int s = kt & 1;
        cp_wait<1>();          // tile kt resident
        __syncthreads();
#pragma unroll
        for (int kk = 0; kk < 16; kk += 8) {
            uint32_t af[2][4], bf[8][2];
#pragma unroll
            for (int mt = 0; mt < 2; mt++) {
                int rb = wm + mt * 16 + gid;
                af[mt][0] = f2tf(As[s][rb][kk + tig]);
                af[mt][1] = f2tf(As[s][rb + 8][kk + tig]);
                af[mt][2] = f2tf(As[s][rb][kk + tig + 4]);
                af[mt][3] = f2tf(As[s][rb + 8][kk + tig + 4]);
            }
#pragma unroll
            for (int nt = 0; nt < 8; nt++) {
                int cb = wn + nt * 8 + gid;
                bf[nt][0] = f2tf(Bs[s][kk + tig][cb]);
                bf[nt][1] = f2tf(Bs[s][kk + 4 + tig][cb]);
            }
#pragma unroll
            for (int mt = 0; mt < 2; mt++)
#pragma unroll
                for (int nt = 0; nt < 8; nt++)
                    mma_tf32(c[mt][nt][0], c[mt][nt][1], c[mt][nt][2], c[mt][nt][3],
                             af[mt][0], af[mt][1], af[mt][2], af[mt][3],
                             bf[nt][0], bf[nt][1]);
        }
        __syncthreads();       // all warps done reading stage s
        if (kt + 2 < ktiles) LOAD_TILE(kt + 2, s);
        cp_commit();
    }
#undef LOAD_TILE

    // epilogue
#pragma unroll
    for (int mt = 0; mt < 2; mt++) {
        int gr0 = brow + wm + mt * 16 + gid;
        int gr1 = gr0 + 8;
#pragma unroll
        for (int nt = 0; nt < 8; nt++) {
            int gc = bcol + wn + nt * 8 + tig * 2;
            float2 bsv = *(const float2*)&bias[gc];
            float2 o0, o1;
            o0.x = c[mt][nt][0] + bsv.x; o0.y = c[mt][nt][1] + bsv.y;
            o1.x = c[mt][nt][2] + bsv.x; o1.y = c[mt][nt][3] + bsv.y;
            if (HAS_RES) {
                float2 r0 = *(const float2*)&res[(size_t)gr0 * N + gc];
                float2 r1 = *(const float2*)&res[(size_t)gr1 * N + gc];
                o0.x += r0.x; o0.y += r0.y;
                o1.x += r1.x; o1.y += r1.y;
            }
            if (ACT) {
                o0.x = fmaxf(o0.x, 0.f); o0.y = fmaxf(o0.y, 0.f);
                o1.x = fmaxf(o1.x, 0.f); o1.y = fmaxf(o1.y, 0.f);
            }
            *(float2*)&C[(size_t)gr0 * N + gc] = o0;
            *(float2*)&C[(size_t)gr1 * N + gc] = o1;
        }
    }
}

// ---------------- fused scores + softmax ----------------
__global__ __launch_bounds__(512) void scores_softmax_kernel(
    const float* __restrict__ q, const float* __restrict__ k,
    float* __restrict__ attn) {
    __shared__ uint32_t Qs[64][65];   // [dk][qrow]
    __shared__ uint32_t Ks[64][65];   // [dk][key]
    __shared__ float redm[64][4];
    __shared__ float reds[64][4];

    int bh = blockIdx.y, b = bh >> 3, h = bh & 7;
    int q0 = blockIdx.x * 64;
    int tid = threadIdx.x;
    int lane = tid & 31, warp = tid >> 5;
    int gid = lane >> 2, tig = lane & 3;
    int wm = warp >> 2, wn = warp & 3;

    int qr = tid >> 3, dkb = (tid & 7) * 8;
    {
        const float* qp = q + (size_t)(b * SS + q0 + qr) * DD + h * DKH + dkb;
        float4 t0 = *(const float4*)qp;
        float4 t1 = *(const float4*)(qp + 4);
        Qs[dkb + 0][qr] = f2tf(t0.x); Qs[dkb + 1][qr] = f2tf(t0.y);
        Qs[dkb + 2][qr] = f2tf(t0.z); Qs[dkb + 3][qr] = f2tf(t0.w);
        Qs[dkb + 4][qr] = f2tf(t1.x); Qs[dkb + 5][qr] = f2tf(t1.y);
        Qs[dkb + 6][qr] = f2tf(t1.z); Qs[dkb + 7][qr] = f2tf(t1.w);
    }

    float s[8][2][4];
#pragma unroll
    for (int nc = 0; nc < 8; nc++)
#pragma unroll
        for (int nt = 0; nt < 2; nt++)
#pragma unroll
            for (int i = 0; i < 4; i++) s[nc][nt][i] = 0.f;

    for (int nc = 0; nc < 8; nc++) {
        __syncthreads();
        {
            const float* kp = k + (size_t)(b * SS + nc * 64 + qr) * DD + h * DKH + dkb;
            float4 t0 = *(const float4*)kp;
            float4 t1 = *(const float4*)(kp + 4);
            Ks[dkb + 0][qr] = f2tf(t0.x); Ks[dkb + 1][qr] = f2tf(t0.y);
            Ks[dkb + 2][qr] = f2tf(t0.z); Ks[dkb + 3][qr] = f2tf(t0.w);
            Ks[dkb + 4][qr] = f2tf(t1.x); Ks[dkb + 5][qr] = f2tf(t1.y);
            Ks[dkb + 6][qr] = f2tf(t1.z); Ks[dkb + 7][qr] = f2tf(t1.w);
        }
        __syncthreads();
#pragma unroll
        for (int kk = 0; kk < 64; kk += 8) {
            uint32_t af[4], bf[2][2];
            int rb = wm * 16 + gid;
            af[0] = Qs[kk + tig][rb];
            af[1] = Qs[kk + tig][rb + 8];
            af[2] = Qs[kk + 4 + tig][rb];
            af[3] = Qs[kk + 4 + tig][rb + 8];
#pragma unroll
            for (int nt = 0; nt < 2; nt++) {
                int cb = wn * 16 + nt * 8 + gid;
                bf[nt][0] = Ks[kk + tig][cb];
                bf[nt][1] = Ks[kk + 4 + tig][cb];
            }
#pragma unroll
            for (int nt = 0; nt < 2; nt++)
                mma_tf32(s[nc][nt][0], s[nc][nt][1], s[nc][nt][2], s[nc][nt][3],
                         af[0], af[1], af[2], af[3], bf[nt][0], bf[nt][1]);
        }
    }

    const float scale = 0.125f;
    int r0 = wm * 16 + gid, r1 = r0 + 8;
    float m0 = -1e30f, m1 = -1e30f;
#pragma unroll
    for (int nc = 0; nc < 8; nc++)
#pragma unroll
        for (int nt = 0; nt < 2; nt++) {
            s[nc][nt][0] *= scale; s[nc][nt][1] *= scale;
            s[nc][nt][2] *= scale; s[nc][nt][3] *= scale;
            m0 = fmaxf(m0, fmaxf(s[nc][nt][0], s[nc][nt][1]));
            m1 = fmaxf(m1, fmaxf(s[nc][nt][2], s[nc][nt][3]));
        }
#pragma unroll
    for (int o = 1; o <= 2; o <<= 1) {
        m0 = fmaxf(m0, __shfl_xor_sync(0xffffffffu, m0, o));
        m1 = fmaxf(m1, __shfl_xor_sync(0xffffffffu, m1, o));
    }
    if (tig == 0) { redm[r0][wn] = m0; redm[r1][wn] = m1; }
    __syncthreads();
    m0 = fmaxf(fmaxf(redm[r0][0], redm[r0][1]), fmaxf(redm[r0][2], redm[r0][3]));
    m1 = fmaxf(fmaxf(redm[r1][0], redm[r1][1]), fmaxf(redm[r1][2], redm[r1][3]));

    float sum0 = 0.f, sum1 = 0.f;
#pragma unroll
    for (int nc = 0; nc < 8; nc++)
#pragma unroll
        for (int nt = 0; nt < 2; nt++) {
            s[nc][nt][0] = __expf(s[nc][nt][0] - m0);
            s[nc][nt][1] = __expf(s[nc][nt][1] - m0);
            s[nc][nt][2] = __expf(s[nc][nt][2] - m1);
            s[nc][nt][3] = __expf(s[nc][nt][3] - m1);
            sum0 += s[nc][nt][0] + s[nc][nt][1];
            sum1 += s[nc][nt][2] + s[nc][nt][3];
        }
#pragma unroll
    for (int o = 1; o <= 2; o <<= 1) {
        sum0 += __shfl_xor_sync(0xffffffffu, sum0, o);
        sum1 += __shfl_xor_sync(0xffffffffu, sum1, o);
    }
    if (tig == 0) { reds[r0][wn] = sum0; reds[r1][wn] = sum1; }
    __syncthreads();
    float inv0 = 1.0f / (reds[r0][0] + reds[r0][1] + reds[r0][2] + reds[r0][3]);
    float inv1 = 1.0f / (reds[r1][0] + reds[r1][1] + reds[r1][2] + reds[r1][3]);

    float* ob = attn + (size_t)bh * SS * SS;
#pragma unroll
    for (int nc = 0; nc < 8; nc++)
#pragma unroll
        for (int nt = 0; nt < 2; nt++) {
            int col = nc * 64 + wn * 16 + nt * 8 + tig * 2;
            float2 o0, o1;
            o0.x = s[nc][nt][0] * inv0; o0.y = s[nc][nt][1] * inv0;
            o1.x = s[nc][nt][2] * inv1; o1.y = s[nc][nt][3] * inv1;
            *(float2*)&ob[(size_t)(q0 + r0) * SS + col] = o0;
            *(float2*)&ob[(size_t)(q0 + r1) * SS + col] = o1;
        }
}

// ---------------- ctx = attn @ V (tf32 mma) ----------------
__global__ __launch_bounds__(256) void ctx_mma_kernel(
    const float* __restrict__ attn, const float* __restrict__ v,
    float* __restrict__ ctx) {
    __shared__ uint32_t As[32][65];   // [key][qrow], transposed probs
    __shared__ uint32_t Bs[32][68];   // [key][dk]

    int bh = blockIdx.y, b = bh >> 3, h = bh & 7;
    int q0 = blockIdx.x * 64;
    int tid = threadIdx.x;
    int lane = tid & 31, warp = tid >> 5;
    int gid = lane >> 2, tig = lane & 3;
    int wm = warp >> 1, wn = warp & 1;

    float c[4][4];
#pragma unroll
    for (int nt = 0; nt < 4; nt++)
#pragma unroll
        for (int i = 0; i < 4; i++) c[nt][i] = 0.f;

    const float* ab = attn + (size_t)bh * SS * SS;
    int am = tid >> 2, akb = (tid & 3) * 8;
    int bk = tid >> 3, bnb = (tid & 7) * 8;

    for (int kt = 0; kt < SS; kt += 32) {
        float4 la0 = *(const float4*)(ab + (size_t)(q0 + am) * SS + kt + akb);
        float4 la1 = *(const float4*)(ab + (size_t)(q0 + am) * SS + kt + akb + 4);
        As[akb + 0][am] = f2tf(la0.x); As[akb + 1][am] = f2tf(la0.y);
        As[akb + 2][am] = f2tf(la0.z); As[akb + 3][am] = f2tf(la0.w);
        As[akb + 4][am] = f2tf(la1.x); As[akb + 5][am] = f2tf(la1.y);
        As[akb + 6][am] = f2tf(la1.z); As[akb + 7][am] = f2tf(la1.w);
        const float* vp = v + (size_t)(b * SS + kt + bk) * DD + h * DKH + bnb;
        float4 lb0 = *(const float4*)vp;
        float4 lb1 = *(const float4*)(vp + 4);
        Bs[bk][bnb + 0] = f2tf(lb0.x); Bs[bk][bnb + 1] = f2tf(lb0.y);
        Bs[bk][bnb + 2] = f2tf(lb0.z); Bs[bk][bnb + 3] = f2tf(lb0.w);
        Bs[bk][bnb + 4] = f2tf(lb1.x); Bs[bk][bnb + 5] = f2tf(lb1.y);
        Bs[bk][bnb + 6] = f2tf(lb1.z); Bs[bk][bnb + 7] = f2tf(lb1.w);
        __syncthreads();
#pragma unroll
        for (int kk = 0; kk < 32; kk += 8) {
            uint32_t af[4], bf[4][2];
            int rb = wm * 16 + gid;
            af[0] = As[kk + tig][rb];
            af[1] = As[kk + tig][rb + 8];
            af[2] = As[kk + 4 + tig][rb];
            af[3] = As[kk + 4 + tig][rb + 8];
#pragma unroll
            for (int nt = 0; nt < 4; nt++) {
                int cb = wn * 32 + nt * 8 + gid;
                bf[nt][0] = Bs[kk + tig][cb];
                bf[nt][1] = Bs[kk + 4 + tig][cb];
            }
#pragma unroll
            for (int nt = 0; nt < 4; nt++)
                mma_tf32(c[nt][0], c[nt][1], c[nt][2], c[nt][3],
                         af[0], af[1], af[2], af[3], bf[nt][0], bf[nt][1]);
        }
        __syncthreads();
    }
#pragma unroll
    for (int nt = 0; nt < 4; nt++) {
        int gr0 = b * SS + q0 + wm * 16 + gid;
        int gc = h * DKH + wn * 32 + nt * 8 + tig * 2;
        *(float2*)&ctx[(size_t)gr0 * DD + gc] = make_float2(c[nt][0], c[nt][1]);
        *(float2*)&ctx[(size_t)(gr0 + 8) * DD + gc] = make_float2(c[nt][2], c[nt][3]);
    }
}

// ---------------- LayerNorm (residual already included in input): warp per row ------
__global__ void ln_kernel(const float* __restrict__ in, const float* __restrict__ g,
                          const float* __restrict__ b, float* __restrict__ out) {
    int row = blockIdx.x * 8 + (threadIdx.x >> 5);
    int lane = threadIdx.x & 31;
    const float4* p = (const float4*)(in + (size_t)row * DD);
    float4 v[4];
    float s = 0.f;
#pragma unroll
    for (int c = 0; c < 4; c++) {
        v[c] = p[lane + c * 32];
        s += v[c].x + v[c].y + v[c].z + v[c].w;
    }
#pragma unroll
    for (int o = 16; o > 0; o >>= 1) s += __shfl_xor_sync(0xffffffffu, s, o);
    float mean = s * (1.0f / DD);
    float q = 0.f;
#pragma unroll
    for (int c = 0; c < 4; c++) {
        float dx = v[c].x - mean, dy = v[c].y - mean, dz = v[c].z - mean, dw = v[c].w - mean;
        q += dx * dx + dy * dy + dz * dz + dw * dw;
    }
#pragma unroll
    for (int o = 16; o > 0; o >>= 1) q += __shfl_xor_sync(0xffffffffu, q, o);
    float w = rsqrtf(q * (1.0f / DD) + 1e-5f);
    float4* po = (float4*)(out + (size_t)row * DD);
    const float4* pg = (const float4*)g;
    const float4* pb = (const float4*)b;
#pragma unroll
    for (int c = 0; c < 4; c++) {
        float4 g4 = pg[lane + c * 32];
        float4 b4 = pb[lane + c * 32];
        float4 o4;
        o4.x = (v[c].x - mean) * w * g4.x + b4.x;
        o4.y = (v[c].y - mean) * w * g4.y + b4.y;
        o4.z = (v[c].z - mean) * w * g4.z + b4.z;
        o4.w = (v[c].w - mean) * w * g4.w + b4.w;
        po[lane + c * 32] = o4;
    }
}

// ---------------- host driver ----------------
extern "C" void kernel_launch(void* const* d_in, const int* in_sizes, int n_in,
                              void* d_out, int out_size) {
    const float* enc  = (const float*)d_in[0];
    const float* valw = (const float*)d_in[1];
    const float* valb = (const float*)d_in[2];
    const float* pos  = (const float*)d_in[3];
    const float* Wq   = (const float*)d_in[4];
    const float* bq   = (const float*)d_in[5];
    const float* Wk   = (const float*)d_in[6];
    const float* bk   = (const float*)d_in[7];
    const float* Wv   = (const float*)d_in[8];
    const float* bv   = (const float*)d_in[9];
    const float* Wo   = (const float*)d_in[10];
    const float* bo   = (const float*)d_in[11];
    const float* ln1g = (const float*)d_in[12];
    const float* ln1b = (const float*)d_in[13];
    const float* c1w  = (const float*)d_in[14];
    const float* c1b  = (const float*)d_in[15];
    const float* c2w  = (const float*)d_in[16];
    const float* c2b  = (const float*)d_in[17];
    const float* ln2g = (const float*)d_in[18];
    const float* ln2b = (const float*)d_in[19];

    float* out_x = (float*)d_out;
    float* out_attn = out_x + (size_t)NT * DD;

    float *x, *q, *k, *v, *ctx, *t, *h;
    cudaGetSymbolAddress((void**)&x,   g_x);
    cudaGetSymbolAddress((void**)&q,   g_q);
    cudaGetSymbolAddress((void**)&k,   g_k);
    cudaGetSymbolAddress((void**)&v,   g_v);
    cudaGetSymbolAddress((void**)&ctx, g_ctx);
    cudaGetSymbolAddress((void**)&t,   g_t);
    cudaGetSymbolAddress((void**)&h,   g_h);

    embed_kernel<<<dim3(DD / 128, NT), 128>>>(enc, valw, valb, pos, x);

    dim3 g512(DD / 128, NT / 128);     // N=512 gemms: (4, 32)
    dim3 gF(FF / 128, NT / 128);       // N=2048 gemm: (16, 32)

    for (int l = 0; l < LL; l++) {
        const float* wq = Wq + (size_t)l * DD * DD;
        const float* wk = Wk + (size_t)l * DD * DD;
        const float* wv = Wv + (size_t)l * DD * DD;
        const float* wo = Wo + (size_t)l * DD * DD;
        float* attn_l = out_attn + (size_t)l * BB * HH * SS * SS;

        mma_gemm<0, 0><<<g512, 256>>>(x, wq, bq + l * DD, nullptr, q, NT, DD, DD);
        mma_gemm<0, 0><<<g512, 256>>>(x, wk, bk + l * DD, nullptr, k, NT, DD, DD);
        mma_gemm<0, 0><<<g512, 256>>>(x, wv, bv + l * DD, nullptr, v, NT, DD, DD);

        scores_softmax_kernel<<<dim3(SS / 64, BB * HH), 512>>>(q, k, attn_l);
        ctx_mma_kernel<<<dim3(SS / 64, BB * HH), 256>>>(attn_l, v, ctx);

        mma_gemm<0, 1><<<g512, 256>>>(ctx, wo, bo + l * DD, x, t, NT, DD, DD);
        ln_kernel<<<NT / 8, 256>>>(t, ln1g + l * DD, ln1b + l * DD, x);

        mma_gemm<1, 0><<<gF, 256>>>(x, c1w + (size_t)l * DD * FF, c1b + l * FF, nullptr, h, NT, FF, DD);
        mma_gemm<0, 1><<<g512, 256>>>(h, c2w + (size_t)l * FF * DD, c2b + l * DD, x, t, NT, DD, FF);

        float* lnout = (l == LL - 1) ? out_x : x;
        ln_kernel<<<NT / 8, 256>>>(t, ln2g + l * DD, ln2b + l * DD, lnout);
    }
}

// round 7
// speedup vs baseline: 2.2857x; 1.0941x over previous
#include <cuda_runtime.h>
#include <cstdint>
#include <cstddef>

#define BB 8
#define SS 512
#define CC 12
#define DD 512
#define HH 8
#define FF 2048
#define LL 4
#define DKH 64
#define NT (BB*SS)   /* 4096 tokens */

// ---------------- scratch (no allocations allowed) ----------------
__device__ float g_x  [NT*DD];
__device__ float g_q  [NT*DD];
__device__ float g_k  [NT*DD];
__device__ float g_v  [NT*DD];
__device__ float g_ctx[NT*DD];
__device__ float g_t  [NT*DD];
__device__ float g_h  [NT*FF];

// ---------------- helpers ----------------
__device__ __forceinline__ uint32_t f2tf(float f) {
    uint32_t u;
    asm("cvt.rna.tf32.f32 %0, %1;" : "=r"(u) : "f"(f));
    return u;
}

__device__ __forceinline__ void mma_tf32(float& c0, float& c1, float& c2, float& c3,
                                         uint32_t a0, uint32_t a1, uint32_t a2, uint32_t a3,
                                         uint32_t b0, uint32_t b1) {
    asm("mma.sync.aligned.m16n8k8.row.col.f32.tf32.tf32.f32 "
        "{%0,%1,%2,%3}, {%4,%5,%6,%7}, {%8,%9}, {%0,%1,%2,%3};"
        : "+f"(c0), "+f"(c1), "+f"(c2), "+f"(c3)
        : "r"(a0), "r"(a1), "r"(a2), "r"(a3), "r"(b0), "r"(b1));
}

__device__ __forceinline__ void cp_async16(void* smem_dst, const void* gsrc) {
    uint32_t s = (uint32_t)__cvta_generic_to_shared(smem_dst);
    asm volatile("cp.async.cg.shared.global [%0], [%1], 16;" :: "r"(s), "l"(gsrc));
}
__device__ __forceinline__ void cp_commit() {
    asm volatile("cp.async.commit_group;");
}
template<int N> __device__ __forceinline__ void cp_wait() {
    asm volatile("cp.async.wait_group %0;" :: "n"(N));
}

// ---------------- embed: x = enc @ val_w + val_b + pos ----------------
__global__ void embed_kernel(const float* __restrict__ enc, const float* __restrict__ vw,
                             const float* __restrict__ vb, const float* __restrict__ pos,
                             float* __restrict__ x) {
    int n = blockIdx.y;
    int d = blockIdx.x * 128 + threadIdx.x;
    int s = n & (SS - 1);
    float acc = vb[d] + pos[s * DD + d];
    const float* er = enc + n * CC;
#pragma unroll
    for (int c = 0; c < CC; c++) acc += er[c] * vw[c * DD + d];
    x[n * DD + d] = acc;
}

// =====================================================================
// GEMM core (BM=128, BN=64, BK=16, 2-stage cp.async, 256 thr, 8 warps)
// warp grid 4(m) x 2(n); warp tile 32x32; accum c[2][4][4].
// =====================================================================
struct G64Frag { float c[2][4][4]; };

__device__ __forceinline__ void g64_mainloop(
    const float* __restrict__ A, const float* __restrict__ W,
    int brow, int bcol, int N, int K,
    float (&As)[2][128][20], float (&Bs)[2][16][72], G64Frag& fr) {
    int tid = threadIdx.x;
    int lane = tid & 31, warp = tid >> 5;
    int gid = lane >> 2, tig = lane & 3;
    int wm = (warp >> 1) * 32, wn = (warp & 1) * 32;

#pragma unroll
    for (int mt = 0; mt < 2; mt++)
#pragma unroll
        for (int nt = 0; nt < 4; nt++)
#pragma unroll
            for (int i = 0; i < 4; i++) fr.c[mt][nt][i] = 0.f;

    int am = tid >> 1, akb = (tid & 1) * 8;        // A: 2 x 16B per thread
    int bkr = tid >> 4, bn = (tid & 15) * 4;       // B: 1 x 16B per thread
    const float* Ap = A + (size_t)(brow + am) * K + akb;
    const float* Bp = W + (size_t)bkr * N + bcol + bn;
    const int ktiles = K >> 4;

#define G64_LOAD(KT, S)                                               \
    do {                                                              \
        const float* _a = Ap + ((KT) << 4);                           \
        cp_async16(&As[S][am][akb],     _a);                          \
        cp_async16(&As[S][am][akb + 4], _a + 4);                      \
        cp_async16(&Bs[S][bkr][bn], Bp + ((size_t)(KT) << 4) * N);    \
    } while (0)

    G64_LOAD(0, 0); cp_commit();
    G64_LOAD(1, 1); cp_commit();

    for (int kt = 0; kt < ktiles; kt++) {
        int s = kt & 1;
        cp_wait<1>();
        __syncthreads();
#pragma unroll
        for (int kk = 0; kk < 16; kk += 8) {
            uint32_t af[2][4], bf[4][2];
#pragma unroll
            for (int mt = 0; mt < 2; mt++) {
                int rb = wm + mt * 16 + gid;
                af[mt][0] = f2tf(As[s][rb][kk + tig]);
                af[mt][1] = f2tf(As[s][rb + 8][kk + tig]);
                af[mt][2] = f2tf(As[s][rb][kk + tig + 4]);
                af[mt][3] = f2tf(As[s][rb + 8][kk + tig + 4]);
            }
#pragma unroll
            for (int nt = 0; nt < 4; nt++) {
                int cb = wn + nt * 8 + gid;
                bf[nt][0] = f2tf(Bs[s][kk + tig][cb]);
                bf[nt][1] = f2tf(Bs[s][kk + 4 + tig][cb]);
            }
#pragma unroll
            for (int mt = 0; mt < 2; mt++)
#pragma unroll
                for (int nt = 0; nt < 4; nt++)
                    mma_tf32(fr.c[mt][nt][0], fr.c[mt][nt][1], fr.c[mt][nt][2], fr.c[mt][nt][3],
                             af[mt][0], af[mt][1], af[mt][2], af[mt][3],
                             bf[nt][0], bf[nt][1]);
        }
        __syncthreads();
        if (kt + 2 < ktiles) G64_LOAD(kt + 2, s);
        cp_commit();
    }
#undef G64_LOAD
}

__device__ __forceinline__ void g64_epilogue(
    const G64Frag& fr, const float* __restrict__ bias, const float* __restrict__ res,
    float* __restrict__ C, int brow, int bcol, int Nout, int ACT, int HAS_RES) {
    int tid = threadIdx.x;
    int lane = tid & 31, warp = tid >> 5;
    int gid = lane >> 2, tig = lane & 3;
    int wm = (warp >> 1) * 32, wn = (warp & 1) * 32;
#pragma unroll
    for (int mt = 0; mt < 2; mt++) {
        int gr0 = brow + wm + mt * 16 + gid;
        int gr1 = gr0 + 8;
#pragma unroll
        for (int nt = 0; nt < 4; nt++) {
            int gc = bcol + wn + nt * 8 + tig * 2;   // output column (bcol < Nout here)
            float2 bsv = *(const float2*)&bias[gc];
            float2 o0, o1;
            o0.x = fr.c[mt][nt][0] + bsv.x; o0.y = fr.c[mt][nt][1] + bsv.y;
            o1.x = fr.c[mt][nt][2] + bsv.x; o1.y = fr.c[mt][nt][3] + bsv.y;
            if (HAS_RES) {
                float2 r0 = *(const float2*)&res[(size_t)gr0 * Nout + gc];
                float2 r1 = *(const float2*)&res[(size_t)gr1 * Nout + gc];
                o0.x += r0.x; o0.y += r0.y;
                o1.x += r1.x; o1.y += r1.y;
            }
            if (ACT) {
                o0.x = fmaxf(o0.x, 0.f); o0.y = fmaxf(o0.y, 0.f);
                o1.x = fmaxf(o1.x, 0.f); o1.y = fmaxf(o1.y, 0.f);
            }
            *(float2*)&C[(size_t)gr0 * Nout + gc] = o0;
            *(float2*)&C[(size_t)gr1 * Nout + gc] = o1;
        }
    }
}

// ---------------- generic BN=64 GEMM ----------------
template<int ACT, int HAS_RES>
__global__ __launch_bounds__(256) void mma_gemm64(
    const float* __restrict__ A, const float* __restrict__ W,
    const float* __restrict__ bias, const float* __restrict__ res,
    float* __restrict__ C, int M, int N, int K) {
    __shared__ float As[2][128][20];
    __shared__ float Bs[2][16][72];
    int brow = blockIdx.y * 128, bcol = blockIdx.x * 64;
    G64Frag fr;
    g64_mainloop(A, W, brow, bcol, N, K, As, Bs, fr);
    g64_epilogue(fr, bias, res, C, brow, bcol, N, ACT, HAS_RES);
}

// ---------------- fused QKV GEMM: grid.x = 24 (3 x 8 tiles of 64) ----------------
__global__ __launch_bounds__(256) void qkv_gemm64(
    const float* __restrict__ A,
    const float* __restrict__ Wq, const float* __restrict__ Wk, const float* __restrict__ Wv,
    const float* __restrict__ bq, const float* __restrict__ bk, const float* __restrict__ bv,
    float* __restrict__ q, float* __restrict__ k, float* __restrict__ v) {
    __shared__ float As[2][128][20];
    __shared__ float Bs[2][16][72];
    int sel = blockIdx.x >> 3;
    int bcol = (blockIdx.x & 7) * 64;
    int brow = blockIdx.y * 128;
    const float* W    = (sel == 0) ? Wq : (sel == 1) ? Wk : Wv;
    const float* bias = (sel == 0) ? bq : (sel == 1) ? bk : bv;
    float* C          = (sel == 0) ? q  : (sel == 1) ? k  : v;
    G64Frag fr;
    g64_mainloop(A, W, brow, bcol, DD, DD, As, Bs, fr);
    g64_epilogue(fr, bias, nullptr, C, brow, bcol, DD, 0, 0);
}

// ---------------- 128x128 GEMM (kept for FFN c1, N=2048) ----------------
template<int ACT, int HAS_RES>
__global__ __launch_bounds__(256) void mma_gemm(
    const float* __restrict__ A, const float* __restrict__ W,
    const float* __restrict__ bias, const float* __restrict__ res,
    float* __restrict__ C, int M, int N, int K) {
    __shared__ float As[2][128][20];
    __shared__ float Bs[2][16][136];

    int tid = threadIdx.x;
    int lane = tid & 31, warp = tid >> 5;
    int gid = lane >> 2, tig = lane & 3;
    int brow = blockIdx.y * 128, bcol = blockIdx.x * 128;
    int wm = (warp >> 1) * 32, wn = (warp & 1) * 64;

    float c[2][8][4];
#pragma unroll
    for (int mt = 0; mt < 2; mt++)
#pragma unroll
        for (int nt = 0; nt < 8; nt++)
#pragma unroll
            for (int i = 0; i < 4; i++) c[mt][nt][i] = 0.f;

    int am = tid >> 1, akb = (tid & 1) * 8;
    int bkr = tid >> 4, bn = (tid & 15) * 8;
    const float* Ap = A + (size_t)(brow + am) * K + akb;
    const float* Bp = W + (size_t)bkr * N + bcol + bn;
    const int ktiles = K >> 4;

#define LOAD_TILE(KT, S)                                              \
    do {                                                              \
        const float* _a = Ap + ((KT) << 4);                           \
        cp_async16(&As[S][am][akb],     _a);                          \
        cp_async16(&As[S][am][akb + 4], _a + 4);                      \
        const float* _b = Bp + ((size_t)(KT) << 4) * N;               \
        cp_async16(&Bs[S][bkr][bn],     _b);                          \
        cp_async16(&Bs[S][bkr][bn + 4], _b + 4);                      \
    } while (0)

    LOAD_TILE(0, 0); cp_commit();
    LOAD_TILE(1, 1); cp_commit();

    for (int kt = 0; kt < ktiles; kt++) {
        int s = kt & 1;
        cp_wait<1>();
        __syncthreads();
#pragma unroll
        for (int kk = 0; kk < 16; kk += 8) {
            uint32_t af[2][4], bf[8][2];
#pragma unroll
            for (int mt = 0; mt < 2; mt++) {
                int rb = wm + mt * 16 + gid;
                af[mt][0] = f2tf(As[s][rb][kk + tig]);
                af[mt][1] = f2tf(As[s][rb + 8][kk + tig]);
                af[mt][2] = f2tf(As[s][rb][kk + tig + 4]);
                af[mt][3] = f2tf(As[s][rb + 8][kk + tig + 4]);
            }
#pragma unroll
            for (int nt = 0; nt < 8; nt++) {
                int cb = wn + nt * 8 + gid;
                bf[nt][0] = f2tf(Bs[s][kk + tig][cb]);
                bf[nt][1] = f2tf(Bs[s][kk + 4 + tig][cb]);
            }
#pragma unroll
            for (int mt = 0; mt < 2; mt++)
#pragma unroll
                for (int nt = 0; nt < 8; nt++)
                    mma_tf32(c[mt][nt][0], c[mt][nt][1], c[mt][nt][2], c[mt][nt][3],
                             af[mt][0], af[mt][1], af[mt][2], af[mt][3],
                             bf[nt][0], bf[nt][1]);
        }
        __syncthreads();
        if (kt + 2 < ktiles) LOAD_TILE(kt + 2, s);
        cp_commit();
    }
#undef LOAD_TILE

#pragma unroll
    for (int mt = 0; mt < 2; mt++) {
        int gr0 = brow + wm + mt * 16 + gid;
        int gr1 = gr0 + 8;
#pragma unroll
        for (int nt = 0; nt < 8; nt++) {
            int gc = bcol + wn + nt * 8 + tig * 2;
            float2 bsv = *(const float2*)&bias[gc];
            float2 o0, o1;
            o0.x = c[mt][nt][0] + bsv.x; o0.y = c[mt][nt][1] + bsv.y;
            o1.x = c[mt][nt][2] + bsv.x; o1.y = c[mt][nt][3] + bsv.y;
            if (HAS_RES) {
                float2 r0 = *(const float2*)&res[(size_t)gr0 * N + gc];
                float2 r1 = *(const float2*)&res[(size_t)gr1 * N + gc];
                o0.x += r0.x; o0.y += r0.y;
                o1.x += r1.x; o1.y += r1.y;
            }
            if (ACT) {
                o0.x = fmaxf(o0.x, 0.f); o0.y = fmaxf(o0.y, 0.f);
                o1.x = fmaxf(o1.x, 0.f); o1.y = fmaxf(o1.y, 0.f);
            }
            *(float2*)&C[(size_t)gr0 * N + gc] = o0;
            *(float2*)&C[(size_t)gr1 * N + gc] = o1;
        }
    }
}

// ---------------- fused scores + softmax ----------------
__global__ __launch_bounds__(512) void scores_softmax_kernel(
    const float* __restrict__ q, const float* __restrict__ k,
    float* __restrict__ attn) {
    __shared__ uint32_t Qs[64][65];   // [dk][qrow]
    __shared__ uint32_t Ks[64][65];   // [dk][key]
    __shared__ float redm[64][4];
    __shared__ float reds[64][4];

    int bh = blockIdx.y, b = bh >> 3, h = bh & 7;
    int q0 = blockIdx.x * 64;
    int tid = threadIdx.x;
    int lane = tid & 31, warp = tid >> 5;
    int gid = lane >> 2, tig = lane & 3;
    int wm = warp >> 2, wn = warp & 3;

    int qr = tid >> 3, dkb = (tid & 7) * 8;
    {
        const float* qp = q + (size_t)(b * SS + q0 + qr) * DD + h * DKH + dkb;
        float4 t0 = *(const float4*)qp;
        float4 t1 = *(const float4*)(qp + 4);
        Qs[dkb + 0][qr] = f2tf(t0.x); Qs[dkb + 1][qr] = f2tf(t0.y);
        Qs[dkb + 2][qr] = f2tf(t0.z); Qs[dkb + 3][qr] = f2tf(t0.w);
        Qs[dkb + 4][qr] = f2tf(t1.x); Qs[dkb + 5][qr] = f2tf(t1.y);
        Qs[dkb + 6][qr] = f2tf(t1.z); Qs[dkb + 7][qr] = f2tf(t1.w);
    }

    float s[8][2][4];
#pragma unroll
    for (int nc = 0; nc < 8; nc++)
#pragma unroll
        for (int nt = 0; nt < 2; nt++)
#pragma unroll
            for (int i = 0; i < 4; i++) s[nc][nt][i] = 0.f;

    for (int nc = 0; nc < 8; nc++) {
        __syncthreads();
        {
            const float* kp = k + (size_t)(b * SS + nc * 64 + qr) * DD + h * DKH + dkb;
            float4 t0 = *(const float4*)kp;
            float4 t1 = *(const float4*)(kp + 4);
            Ks[dkb + 0][qr] = f2tf(t0.x); Ks[dkb + 1][qr] = f2tf(t0.y);
            Ks[dkb + 2][qr] = f2tf(t0.z); Ks[dkb + 3][qr] = f2tf(t0.w);
            Ks[dkb + 4][qr] = f2tf(t1.x); Ks[dkb + 5][qr] = f2tf(t1.y);
            Ks[dkb + 6][qr] = f2tf(t1.z); Ks[dkb + 7][qr] = f2tf(t1.w);
        }
        __syncthreads();
#pragma unroll
        for (int kk = 0; kk < 64; kk += 8) {
            uint32_t af[4], bf[2][2];
            int rb = wm * 16 + gid;
            af[0] = Qs[kk + tig][rb];
            af[1] = Qs[kk + tig][rb + 8];
            af[2] = Qs[kk + 4 + tig][rb];
            af[3] = Qs[kk + 4 + tig][rb + 8];
#pragma unroll
            for (int nt = 0; nt < 2; nt++) {
                int cb = wn * 16 + nt * 8 + gid;
                bf[nt][0] = Ks[kk + tig][cb];
                bf[nt][1] = Ks[kk + 4 + tig][cb];
            }
#pragma unroll
            for (int nt = 0; nt < 2; nt++)
                mma_tf32(s[nc][nt][0], s[nc][nt][1], s[nc][nt][2], s[nc][nt][3],
                         af[0], af[1], af[2], af[3], bf[nt][0], bf[nt][1]);
        }
    }

    const float scale = 0.125f;
    int r0 = wm * 16 + gid, r1 = r0 + 8;
    float m0 = -1e30f, m1 = -1e30f;
#pragma unroll
    for (int nc = 0; nc < 8; nc++)
#pragma unroll
        for (int nt = 0; nt < 2; nt++) {
            s[nc][nt][0] *= scale; s[nc][nt][1] *= scale;
            s[nc][nt][2] *= scale; s[nc][nt][3] *= scale;
            m0 = fmaxf(m0, fmaxf(s[nc][nt][0], s[nc][nt][1]));
            m1 = fmaxf(m1, fmaxf(s[nc][nt][2], s[nc][nt][3]));
        }
#pragma unroll
    for (int o = 1; o <= 2; o <<= 1) {
        m0 = fmaxf(m0, __shfl_xor_sync(0xffffffffu, m0, o));
        m1 = fmaxf(m1, __shfl_xor_sync(0xffffffffu, m1, o));
    }
    if (tig == 0) { redm[r0][wn] = m0; redm[r1][wn] = m1; }
    __syncthreads();
    m0 = fmaxf(fmaxf(redm[r0][0], redm[r0][1]), fmaxf(redm[r0][2], redm[r0][3]));
    m1 = fmaxf(fmaxf(redm[r1][0], redm[r1][1]), fmaxf(redm[r1][2], redm[r1][3]));

    float sum0 = 0.f, sum1 = 0.f;
#pragma unroll
    for (int nc = 0; nc < 8; nc++)
#pragma unroll
        for (int nt = 0; nt < 2; nt++) {
            s[nc][nt][0] = __expf(s[nc][nt][0] - m0);
            s[nc][nt][1] = __expf(s[nc][nt][1] - m0);
            s[nc][nt][2] = __expf(s[nc][nt][2] - m1);
            s[nc][nt][3] = __expf(s[nc][nt][3] - m1);
            sum0 += s[nc][nt][0] + s[nc][nt][1];
            sum1 += s[nc][nt][2] + s[nc][nt][3];
        }
#pragma unroll
    for (int o = 1; o <= 2; o <<= 1) {
        sum0 += __shfl_xor_sync(0xffffffffu, sum0, o);
        sum1 += __shfl_xor_sync(0xffffffffu, sum1, o);
    }
    if (tig == 0) { reds[r0][wn] = sum0; reds[r1][wn] = sum1; }
    __syncthreads();
    float inv0 = 1.0f / (reds[r0][0] + reds[r0][1] + reds[r0][2] + reds[r0][3]);
    float inv1 = 1.0f / (reds[r1][0] + reds[r1][1] + reds[r1][2] + reds[r1][3]);

    float* ob = attn + (size_t)bh * SS * SS;
#pragma unroll
    for (int nc = 0; nc < 8; nc++)
#pragma unroll
        for (int nt = 0; nt < 2; nt++) {
            int col = nc * 64 + wn * 16 + nt * 8 + tig * 2;
            float2 o0, o1;
            o0.x = s[nc][nt][0] * inv0; o0.y = s[nc][nt][1] * inv0;
            o1.x = s[nc][nt][2] * inv1; o1.y = s[nc][nt][3] * inv1;
            *(float2*)&ob[(size_t)(q0 + r0) * SS + col] = o0;
            *(float2*)&ob[(size_t)(q0 + r1) * SS + col] = o1;
        }
}

// ---------------- ctx = attn @ V (tf32 mma) ----------------
__global__ __launch_bounds__(256) void ctx_mma_kernel(
    const float* __restrict__ attn, const float* __restrict__ v,
    float* __restrict__ ctx) {
    __shared__ uint32_t As[32][65];   // [key][qrow], transposed probs
    __shared__ uint32_t Bs[32][68];   // [key][dk]

    int bh = blockIdx.y, b = bh >> 3, h = bh & 7;
    int q0 = blockIdx.x * 64;
    int tid = threadIdx.x;
    int lane = tid & 31, warp = tid >> 5;
    int gid = lane >> 2, tig = lane & 3;
    int wm = warp >> 1, wn = warp & 1;

    float c[4][4];
#pragma unroll
    for (int nt = 0; nt < 4; nt++)
#pragma unroll
        for (int i = 0; i < 4; i++) c[nt][i] = 0.f;

    const float* ab = attn + (size_t)bh * SS * SS;
    int am = tid >> 2, akb = (tid & 3) * 8;
    int bk = tid >> 3, bnb = (tid & 7) * 8;

    for (int kt = 0; kt < SS; kt += 32) {
        float4 la0 = *(const float4*)(ab + (size_t)(q0 + am) * SS + kt + akb);
        float4 la1 = *(const float4*)(ab + (size_t)(q0 + am) * SS + kt + akb + 4);
        As[akb + 0][am] = f2tf(la0.x); As[akb + 1][am] = f2tf(la0.y);
        As[akb + 2][am] = f2tf(la0.z); As[akb + 3][am] = f2tf(la0.w);
        As[akb + 4][am] = f2tf(la1.x); As[akb + 5][am] = f2tf(la1.y);
        As[akb + 6][am] = f2tf(la1.z); As[akb + 7][am] = f2tf(la1.w);
        const float* vp = v + (size_t)(b * SS + kt + bk) * DD + h * DKH + bnb;
        float4 lb0 = *(const float4*)vp;
        float4 lb1 = *(const float4*)(vp + 4);
        Bs[bk][bnb + 0] = f2tf(lb0.x); Bs[bk][bnb + 1] = f2tf(lb0.y);
        Bs[bk][bnb + 2] = f2tf(lb0.z); Bs[bk][bnb + 3] = f2tf(lb0.w);
        Bs[bk][bnb + 4] = f2tf(lb1.x); Bs[bk][bnb + 5] = f2tf(lb1.y);
        Bs[bk][bnb + 6] = f2tf(lb1.z); Bs[bk][bnb + 7] = f2tf(lb1.w);
        __syncthreads();
#pragma unroll
        for (int kk = 0; kk < 32; kk += 8) {
            uint32_t af[4], bf[4][2];
            int rb = wm * 16 + gid;
            af[0] = As[kk + tig][rb];
            af[1] = As[kk + tig][rb + 8];
            af[2] = As[kk + 4 + tig][rb];
            af[3] = As[kk + 4 + tig][rb + 8];
#pragma unroll
            for (int nt = 0; nt < 4; nt++) {
                int cb = wn * 32 + nt * 8 + gid;
                bf[nt][0] = Bs[kk + tig][cb];
                bf[nt][1] = Bs[kk + 4 + tig][cb];
            }
#pragma unroll
            for (int nt = 0; nt < 4; nt++)
                mma_tf32(c[nt][0], c[nt][1], c[nt][2], c[nt][3],
                         af[0], af[1], af[2], af[3], bf[nt][0], bf[nt][1]);
        }
        __syncthreads();
    }
#pragma unroll
    for (int nt = 0; nt < 4; nt++) {
        int gr0 = b * SS + q0 + wm * 16 + gid;
        int gc = h * DKH + wn * 32 + nt * 8 + tig * 2;
        *(float2*)&ctx[(size_t)gr0 * DD + gc] = make_float2(c[nt][0], c[nt][1]);
        *(float2*)&ctx[(size_t)(gr0 + 8) * DD + gc] = make_float2(c[nt][2], c[nt][3]);
    }
}

// ---------------- LayerNorm (residual already included in input): warp per row ------
__global__ void ln_kernel(const float* __restrict__ in, const float* __restrict__ g,
                          const float* __restrict__ b, float* __restrict__ out) {
    int row = blockIdx.x * 8 + (threadIdx.x >> 5);
    int lane = threadIdx.x & 31;
    const float4* p = (const float4*)(in + (size_t)row * DD);
    float4 v[4];
    float s = 0.f;
#pragma unroll
    for (int c = 0; c < 4; c++) {
        v[c] = p[lane + c * 32];
        s += v[c].x + v[c].y + v[c].z + v[c].w;
    }
#pragma unroll
    for (int o = 16; o > 0; o >>= 1) s += __shfl_xor_sync(0xffffffffu, s, o);
    float mean = s * (1.0f / DD);
    float q = 0.f;
#pragma unroll
    for (int c = 0; c < 4; c++) {
        float dx = v[c].x - mean, dy = v[c].y - mean, dz = v[c].z - mean, dw = v[c].w - mean;
        q += dx * dx + dy * dy + dz * dz + dw * dw;
    }
#pragma unroll
    for (int o = 16; o > 0; o >>= 1) q += __shfl_xor_sync(0xffffffffu, q, o);
    float w = rsqrtf(q * (1.0f / DD) + 1e-5f);
    float4* po = (float4*)(out + (size_t)row * DD);
    const float4* pg = (const float4*)g;
    const float4* pb = (const float4*)b;
#pragma unroll
    for (int c = 0; c < 4; c++) {
        float4 g4 = pg[lane + c * 32];
        float4 b4 = pb[lane + c * 32];
        float4 o4;
        o4.x = (v[c].x - mean) * w * g4.x + b4.x;
        o4.y = (v[c].y - mean) * w * g4.y + b4.y;
        o4.z = (v[c].z - mean) * w * g4.z + b4.z;
        o4.w = (v[c].w - mean) * w * g4.w + b4.w;
        po[lane + c * 32] = o4;
    }
}

// ---------------- host driver ----------------
extern "C" void kernel_launch(void* const* d_in, const int* in_sizes, int n_in,
                              void* d_out, int out_size) {
    const float* enc  = (const float*)d_in[0];
    const float* valw = (const float*)d_in[1];
    const float* valb = (const float*)d_in[2];
    const float* pos  = (const float*)d_in[3];
    const float* Wq   = (const float*)d_in[4];
    const float* bq   = (const float*)d_in[5];
    const float* Wk   = (const float*)d_in[6];
    const float* bk   = (const float*)d_in[7];
    const float* Wv   = (const float*)d_in[8];
    const float* bv   = (const float*)d_in[9];
    const float* Wo   = (const float*)d_in[10];
    const float* bo   = (const float*)d_in[11];
    const float* ln1g = (const float*)d_in[12];
    const float* ln1b = (const float*)d_in[13];
    const float* c1w  = (const float*)d_in[14];
    const float* c1b  = (const float*)d_in[15];
    const float* c2w  = (const float*)d_in[16];
    const float* c2b  = (const float*)d_in[17];
    const float* ln2g = (const float*)d_in[18];
    const float* ln2b = (const float*)d_in[19];

    float* out_x = (float*)d_out;
    float* out_attn = out_x + (size_t)NT * DD;

    float *x, *q, *k, *v, *ctx, *t, *h;
    cudaGetSymbolAddress((void**)&x,   g_x);
    cudaGetSymbolAddress((void**)&q,   g_q);
    cudaGetSymbolAddress((void**)&k,   g_k);
    cudaGetSymbolAddress((void**)&v,   g_v);
    cudaGetSymbolAddress((void**)&ctx, g_ctx);
    cudaGetSymbolAddress((void**)&t,   g_t);
    cudaGetSymbolAddress((void**)&h,   g_h);

    embed_kernel<<<dim3(DD / 128, NT), 128>>>(enc, valw, valb, pos, x);

    dim3 gQKV(24, NT / 128);           // fused QKV: 768 CTAs
    dim3 g64(DD / 64, NT / 128);       // N=512 BN=64: 256 CTAs
    dim3 gF(FF / 128, NT / 128);       // N=2048 gemm: 512 CTAs

    for (int l = 0; l < LL; l++) {
        const float* wq = Wq + (size_t)l * DD * DD;
        const float* wk = Wk + (size_t)l * DD * DD;
        const float* wv = Wv + (size_t)l * DD * DD;
        const float* wo = Wo + (size_t)l * DD * DD;
        float* attn_l = out_attn + (size_t)l * BB * HH * SS * SS;

        qkv_gemm64<<<gQKV, 256>>>(x, wq, wk, wv, bq + l * DD, bk + l * DD, bv + l * DD,
                                  q, k, v);

        scores_softmax_kernel<<<dim3(SS / 64, BB * HH), 512>>>(q, k, attn_l);
        ctx_mma_kernel<<<dim3(SS / 64, BB * HH), 256>>>(attn_l, v, ctx);

        mma_gemm64<0, 1><<<g64, 256>>>(ctx, wo, bo + l * DD, x, t, NT, DD, DD);
        ln_kernel<<<NT / 8, 256>>>(t, ln1g + l * DD, ln1b + l * DD, x);

        mma_gemm<1, 0><<<gF, 256>>>(x, c1w + (size_t)l * DD * FF, c1b + l * FF, nullptr, h, NT, FF, DD);
        mma_gemm64<0, 1><<<g64, 256>>>(h, c2w + (size_t)l * FF * DD, c2b + l * DD, x, t, NT, DD, FF);

        float* lnout = (l == LL - 1) ? out_x : x;
        ln_kernel<<<NT / 8, 256>>>(t, ln2g + l * DD, ln2b + l * DD, lnout);
    }
}